// round 8
// baseline (speedup 1.0000x reference)
#include <cuda_runtime.h>
#include <cuda_bf16.h>
#include <cstdint>
#include <cfloat>

#define NB      4096
#define NDIM    128
#define BT      128         // tile size (rows and cols)
#define KS      32          // k-stage size
#define NRT     (NB / BT)   // 32 row tiles
#define NPAIRS  (NRT * (NRT + 1) / 2)   // 528 triangular tile pairs
#define NTHREADS 256
#define NCLASS  100
#define MAXMEM  64

typedef unsigned long long u64;

// ---------------- device scratch (static, no allocation) --------------------
__device__ float g_embT[NDIM * NB];
__device__ float g_sqnorm[NB];
__device__ u64   g_best[NB];   // packed (value,idx) argmax, neg
__device__ int   g_posidx[NB];
__device__ float g_loss[NB];
__device__ float g_cnt[NB];
__device__ int   g_ccnt[NCLASS];
__device__ int   g_members[NCLASS * MAXMEM];

// ---------------- packed f32x2 FMA (Blackwell) -------------------------------
__device__ __forceinline__ u64 ffma2(u64 a, u64 b, u64 c) {
    u64 d;
    asm("fma.rn.f32x2 %0, %1, %2, %3;" : "=l"(d) : "l"(a), "l"(b), "l"(c));
    return d;
}
__device__ __forceinline__ u64 dup_f32(float x) {
    u64 d;
    asm("mov.b64 %0, {%1, %1};" : "=l"(d) : "f"(x));
    return d;
}

// ---------------- threefry2x32 ----------------------------------------------
__host__ __device__ __forceinline__ void tf2x32(uint32_t k0, uint32_t k1,
                                                uint32_t c0, uint32_t c1,
                                                uint32_t& o0, uint32_t& o1) {
    const uint32_t ks2 = k0 ^ k1 ^ 0x1BD11BDAu;
    uint32_t x0 = c0 + k0;
    uint32_t x1 = c1 + k1;
#define TFR(r) { x0 += x1; x1 = (x1 << r) | (x1 >> (32 - r)); x1 ^= x0; }
    TFR(13) TFR(15) TFR(26) TFR(6)   x0 += k1;  x1 += ks2 + 1u;
    TFR(17) TFR(29) TFR(16) TFR(24)  x0 += ks2; x1 += k0  + 2u;
    TFR(13) TFR(15) TFR(26) TFR(6)   x0 += k0;  x1 += k1  + 3u;
    TFR(17) TFR(29) TFR(16) TFR(24)  x0 += k1;  x1 += ks2 + 4u;
    TFR(13) TFR(15) TFR(26) TFR(6)   x0 += ks2; x1 += k0  + 5u;
#undef TFR
    o0 = x0; o1 = x1;
}

__device__ __forceinline__ uint32_t jax_bits32(uint32_t k0, uint32_t k1, uint32_t n) {
    uint32_t o0, o1;
    tf2x32(k0, k1, 0u, n, o0, o1);
    return o0 ^ o1;
}

__device__ __forceinline__ float jax_gumbel(uint32_t bits) {
    float f = __uint_as_float((bits >> 9) | 0x3f800000u) - 1.0f;
    float u = fmaxf(f, 1.17549435e-38f);
    float nl = -logf(u);               // accurate: u->1 tail decides winners
    return -__logf(nl);
}

// pack (value, idx) so max() == argmax, first-index tie-break
__device__ __forceinline__ u64 pack_vi(float v, int idx) {
    uint32_t s = __float_as_uint(v);
    s = (s & 0x80000000u) ? ~s : (s | 0x80000000u);
    return ((u64)s << 32) | (uint32_t)(0xFFFFFFFFu - (uint32_t)idx);
}

// ---------------- prep kernels ----------------------------------------------
__global__ void transpose_k(const float* __restrict__ emb) {
    __shared__ float t[32][33];
    int rb = blockIdx.x * 32, kb = blockIdx.y * 32;
    int tx = threadIdx.x, ty = threadIdx.y;
#pragma unroll
    for (int j = 0; j < 4; j++)
        t[ty + j * 8][tx] = emb[(rb + ty + j * 8) * NDIM + kb + tx];
    __syncthreads();
#pragma unroll
    for (int j = 0; j < 4; j++)
        g_embT[(kb + ty + j * 8) * NB + rb + tx] = t[tx][ty + j * 8];
}

__global__ void norm_k(const float* __restrict__ emb) {
    int gid = blockIdx.x * blockDim.x + threadIdx.x;
    if (gid < NCLASS) g_ccnt[gid] = 0;          // reset class bins each launch
    int w = gid >> 5;
    int lane = threadIdx.x & 31;
    if (w >= NB) return;
    float4 v = *(const float4*)(emb + w * NDIM + lane * 4);
    float s = v.x * v.x + v.y * v.y + v.z * v.z + v.w * v.w;
#pragma unroll
    for (int o = 16; o; o >>= 1) s += __shfl_xor_sync(0xFFFFFFFFu, s, o);
    if (lane == 0) { g_sqnorm[w] = s; g_best[w] = 0ull; }   // reset every launch
}

__global__ void bin_k(const int* __restrict__ labels) {
    int i = blockIdx.x * blockDim.x + threadIdx.x;
    if (i >= NB) return;
    int c = labels[i];
    int s = atomicAdd(&g_ccnt[c], 1);
    if (s < MAXMEM) g_members[c * MAXMEM + s] = i;
}

// ---------------- negatives: 128x128 triangular tiles, FFMA2, 8x8 blocking --
__global__ void __launch_bounds__(NTHREADS, 2)
neg_sample_k(const int* __restrict__ labels, uint32_t kn0, uint32_t kn1) {
    extern __shared__ char sm[];
    float* A_s = (float*)sm;                        // [KS][BT] k-major, tile I
    float* B_s = A_s + KS * BT;                     // [KS][BT] k-major, tile J
    int*   labA = (int*)(B_s + KS * BT);            // [128]
    int*   labB = labA + BT;                        // [128]
    float* sqA  = (float*)(labB + BT);              // [128]
    float* sqB  = sqA + BT;                         // [128]
    u64*   redA = (u64*)(sqB + BT);                 // [128]
    u64*   redB = redA + BT;                        // [128]

    const int tid = threadIdx.x;
    const int tr = tid >> 4;          // 0..15, rows tr*8..+7
    const int tc = tid & 15;          // 0..15, cols tc*8..+7

    // decode triangular pair index
    int bid = blockIdx.x;
    int I = (int)((2.0f * NRT + 1.0f
                   - sqrtf((2.0f * NRT + 1.0f) * (2.0f * NRT + 1.0f)
                           - 8.0f * (float)bid)) * 0.5f);
    while (I * (2 * NRT + 1 - I) / 2 > bid) I--;
    while ((I + 1) * (2 * NRT - I) / 2 <= bid) I++;
    const int J = I + (bid - I * (2 * NRT + 1 - I) / 2);
    const int row0 = I * BT;
    const int col0 = J * BT;
    const bool diag = (I == J);

    if (tid < BT) {
        labA[tid] = labels[row0 + tid]; sqA[tid] = g_sqnorm[row0 + tid];
        redA[tid] = 0ull;
    } else {
        int q = tid - BT;
        labB[q] = labels[col0 + q]; sqB[q] = g_sqnorm[col0 + q];
        redB[q] = 0ull;
    }

    u64 acc2[8][4];
#pragma unroll
    for (int r = 0; r < 8; r++)
#pragma unroll
        for (int c = 0; c < 4; c++) acc2[r][c] = 0ull;

    for (int st = 0; st < NDIM / KS; st++) {
        const int k0 = st * KS;
        __syncthreads();
        // load k-stage of both tiles (coalesced float4)
        for (int idx = tid; idx < KS * BT / 4; idx += NTHREADS) {
            int k = idx >> 5;             // BT/4 = 32 float4 per row
            int q = (idx & 31) << 2;
            *(float4*)&A_s[k * BT + q] =
                *(const float4*)&g_embT[(k0 + k) * NB + row0 + q];
            *(float4*)&B_s[k * BT + q] =
                *(const float4*)&g_embT[(k0 + k) * NB + col0 + q];
        }
        __syncthreads();

#pragma unroll 8
        for (int k = 0; k < KS; k++) {
            float4 aLo = *(const float4*)&A_s[k * BT + tr * 8];
            float4 aHi = *(const float4*)&A_s[k * BT + tr * 8 + 4];
            ulonglong2 bLo = *(const ulonglong2*)&B_s[k * BT + tc * 8];
            ulonglong2 bHi = *(const ulonglong2*)&B_s[k * BT + tc * 8 + 4];
            u64 ad[8];
            ad[0] = dup_f32(aLo.x); ad[1] = dup_f32(aLo.y);
            ad[2] = dup_f32(aLo.z); ad[3] = dup_f32(aLo.w);
            ad[4] = dup_f32(aHi.x); ad[5] = dup_f32(aHi.y);
            ad[6] = dup_f32(aHi.z); ad[7] = dup_f32(aHi.w);
#pragma unroll
            for (int r = 0; r < 8; r++) {
                acc2[r][0] = ffma2(ad[r], bLo.x, acc2[r][0]);
                acc2[r][1] = ffma2(ad[r], bLo.y, acc2[r][1]);
                acc2[r][2] = ffma2(ad[r], bHi.x, acc2[r][2]);
                acc2[r][3] = ffma2(ad[r], bHi.y, acc2[r][3]);
            }
        }
    }
    __syncthreads();

    float sqr[8]; int labr[8];
#pragma unroll
    for (int r = 0; r < 8; r++) {
        sqr[r]  = sqA[tr * 8 + r];
        labr[r] = labA[tr * 8 + r];
    }

    u64 best1[8] = {0,0,0,0,0,0,0,0};   // per row (anchor i)
    u64 best2[8] = {0,0,0,0,0,0,0,0};   // per col (anchor j)

#pragma unroll
    for (int cp = 0; cp < 4; cp++) {
#pragma unroll
        for (int h = 0; h < 2; h++) {
            const int cl = tc * 8 + 2 * cp + h;
            const int j  = col0 + cl;
            const int labj = labB[cl];
            const float sqj = sqB[cl];
#pragma unroll
            for (int r = 0; r < 8; r++) {
                if (labr[r] == labj) continue;      // same-label -> -inf logit
                union { u64 u; float2 f; } cv; cv.u = acc2[r][cp];
                const float dot = h ? cv.f.y : cv.f.x;
                const int i = row0 + tr * 8 + r;
                float d2 = (sqr[r] + sqj) - 2.0f * dot;
                d2 = fmaxf(d2, 0.25f);              // == clip d at 0.5
                d2 = fminf(d2, 3.999f);             // guard log(<=0); never hit
                float lq = -63.0f * __logf(d2)
                           - 62.5f * __logf(fmaf(-0.25f, d2, 1.0f));
                {   // orientation 1: anchor i, candidate j
                    uint32_t bits = jax_bits32(kn0, kn1, (uint32_t)(i * NB + j));
                    u64 p = pack_vi(lq + jax_gumbel(bits), j);
                    if (p > best1[r]) best1[r] = p;
                }
                if (!diag) {  // orientation 2: anchor j, candidate i
                    uint32_t bits = jax_bits32(kn0, kn1, (uint32_t)(j * NB + i));
                    u64 p = pack_vi(lq + jax_gumbel(bits), i);
                    if (p > best2[2 * cp + h]) best2[2 * cp + h] = p;
                }
            }
        }
    }

#pragma unroll
    for (int r = 0; r < 8; r++)
        if (best1[r]) atomicMax(&redA[tr * 8 + r], best1[r]);
    if (!diag) {
#pragma unroll
        for (int c = 0; c < 8; c++)
            if (best2[c]) atomicMax(&redB[tc * 8 + c], best2[c]);
    }
    __syncthreads();
    if (tid < BT) {
        if (redA[tid]) atomicMax(&g_best[row0 + tid], redA[tid]);
    } else if (!diag) {
        int q = tid - BT;
        if (redB[q]) atomicMax(&g_best[col0 + q], redB[q]);
    }
}

// ---------------- positives: warp-per-anchor over class member list ---------
__global__ void pos_sample_k(const int* __restrict__ labels,
                             uint32_t kp0, uint32_t kp1) {
    const int t = threadIdx.x;
    const int anchor = (blockIdx.x * 256 + t) >> 5;
    const int lane = t & 31;
    const int li = labels[anchor];
    const int cnt = min(g_ccnt[li], MAXMEM);
    u64 best = 0ull;
    for (int s = lane; s < cnt; s += 32) {
        int j = g_members[li * MAXMEM + s];
        if (j != anchor) {
            uint32_t bits = jax_bits32(kp0, kp1, (uint32_t)(anchor * NB + j));
            u64 p = pack_vi(jax_gumbel(bits), j);
            if (p > best) best = p;
        }
    }
#pragma unroll
    for (int o = 16; o; o >>= 1) {
        u64 q = __shfl_xor_sync(0xFFFFFFFFu, best, o);
        if (q > best) best = q;
    }
    if (lane == 0)
        g_posidx[anchor] = (int)(0xFFFFFFFFu - (uint32_t)best);
}

// ---------------- finalize: per-anchor losses -------------------------------
__global__ void finalize_k(const float* __restrict__ emb,
                           const int* __restrict__ labels,
                           const float* __restrict__ beta) {
    int w = (blockIdx.x * blockDim.x + threadIdx.x) >> 5;
    int lane = threadIdx.x & 31;
    if (w >= NB) return;
    int pi = g_posidx[w];
    int ni = (int)(0xFFFFFFFFu - (uint32_t)g_best[w]);
    float4 a = *(const float4*)(emb + w * NDIM + lane * 4);
    float4 p = *(const float4*)(emb + pi * NDIM + lane * 4);
    float4 n = *(const float4*)(emb + ni * NDIM + lane * 4);
    float dx, sap, san;
    dx = a.x - p.x; sap = dx * dx; dx = a.y - p.y; sap += dx * dx;
    dx = a.z - p.z; sap += dx * dx; dx = a.w - p.w; sap += dx * dx;
    dx = a.x - n.x; san = dx * dx; dx = a.y - n.y; san += dx * dx;
    dx = a.z - n.z; san += dx * dx; dx = a.w - n.w; san += dx * dx;
#pragma unroll
    for (int o = 16; o; o >>= 1) {
        sap += __shfl_xor_sync(0xFFFFFFFFu, sap, o);
        san += __shfl_xor_sync(0xFFFFFFFFu, san, o);
    }
    if (lane == 0) {
        float d_ap = sqrtf(sap + 1e-8f);
        float d_an = sqrtf(san + 1e-8f);
        float ba = beta[labels[w]];
        float pl = fmaxf(d_ap - ba + 0.2f, 0.0f);
        float nl = fmaxf(ba - d_an + 0.2f, 0.0f);
        g_loss[w] = pl + nl;
        g_cnt[w]  = (pl > 0.0f ? 1.0f : 0.0f) + (nl > 0.0f ? 1.0f : 0.0f);
    }
}

__global__ void reduce_k(float* __restrict__ out) {
    __shared__ float st[256], sc[256];
    int t = threadIdx.x;
    float s = 0.f, c = 0.f;
    for (int i = t; i < NB; i += 256) { s += g_loss[i]; c += g_cnt[i]; }
    st[t] = s; sc[t] = c;
    __syncthreads();
    for (int o = 128; o; o >>= 1) {
        if (t < o) { st[t] += st[t + o]; sc[t] += sc[t + o]; }
        __syncthreads();
    }
    if (t == 0) out[0] = (sc[0] == 0.0f) ? st[0] : st[0] / sc[0];
}

// ---------------- host -------------------------------------------------------
extern "C" void kernel_launch(void* const* d_in, const int* in_sizes, int n_in,
                              void* d_out, int out_size) {
    const float* emb    = (const float*)d_in[0];
    const int*   labels = (const int*)d_in[1];
    const float* beta   = (const float*)d_in[2];
    float* out = (float*)d_out;

    uint32_t kn0, kn1, kp0, kp1;
    tf2x32(0u, 42u, 0u, 0u, kn0, kn1);   // foldlike split: k_neg
    tf2x32(0u, 42u, 0u, 1u, kp0, kp1);   // k_pos

    const int smem = 2 * (KS * BT * 4)          // A_s, B_s
                   + 2 * (BT * 4)               // labA, labB
                   + 2 * (BT * 4)               // sqA, sqB
                   + 2 * (BT * 8);              // redA, redB
    cudaFuncSetAttribute(neg_sample_k,
                         cudaFuncAttributeMaxDynamicSharedMemorySize, smem);

    transpose_k<<<dim3(NB / 32, NDIM / 32), dim3(32, 8)>>>(emb);
    norm_k<<<NB * 32 / 256, 256>>>(emb);
    bin_k<<<NB / 256, 256>>>(labels);
    neg_sample_k<<<NPAIRS, NTHREADS, smem>>>(labels, kn0, kn1);
    pos_sample_k<<<NB / 8, 256>>>(labels, kp0, kp1);
    finalize_k<<<NB * 32 / 256, 256>>>(emb, labels, beta);
    reduce_k<<<1, 256>>>(out);
}

// round 9
// speedup vs baseline: 1.2657x; 1.2657x over previous
#include <cuda_runtime.h>
#include <cuda_bf16.h>
#include <cstdint>
#include <cfloat>

#define NB      4096
#define NDIM    128
#define BT      64          // tile size (rows and cols)
#define KS      64          // k-stage size (2 stages)
#define NRT     (NB / BT)   // 64 row tiles
#define NPAIRS  (NRT * (NRT + 1) / 2)   // 2080 triangular tile pairs
#define NTHREADS 256
#define NCLASS  100
#define MAXMEM  64

typedef unsigned long long u64;

// ---------------- device scratch (static, no allocation) --------------------
__device__ float g_embT[NDIM * NB];
__device__ float g_sqnorm[NB];
__device__ u64   g_best[NB];   // packed (value,idx) argmax, neg
__device__ int   g_posidx[NB];
__device__ float g_loss[NB];
__device__ float g_cnt[NB];
__device__ int   g_ccnt[NCLASS];
__device__ int   g_members[NCLASS * MAXMEM];

// ---------------- packed f32x2 FMA (Blackwell) -------------------------------
__device__ __forceinline__ u64 ffma2(u64 a, u64 b, u64 c) {
    u64 d;
    asm("fma.rn.f32x2 %0, %1, %2, %3;" : "=l"(d) : "l"(a), "l"(b), "l"(c));
    return d;
}
__device__ __forceinline__ u64 dup_f32(float x) {
    u64 d;
    asm("mov.b64 %0, {%1, %1};" : "=l"(d) : "f"(x));
    return d;
}

// ---------------- threefry2x32 ----------------------------------------------
__host__ __device__ __forceinline__ void tf2x32(uint32_t k0, uint32_t k1,
                                                uint32_t c0, uint32_t c1,
                                                uint32_t& o0, uint32_t& o1) {
    const uint32_t ks2 = k0 ^ k1 ^ 0x1BD11BDAu;
    uint32_t x0 = c0 + k0;
    uint32_t x1 = c1 + k1;
#define TFR(r) { x0 += x1; x1 = (x1 << r) | (x1 >> (32 - r)); x1 ^= x0; }
    TFR(13) TFR(15) TFR(26) TFR(6)   x0 += k1;  x1 += ks2 + 1u;
    TFR(17) TFR(29) TFR(16) TFR(24)  x0 += ks2; x1 += k0  + 2u;
    TFR(13) TFR(15) TFR(26) TFR(6)   x0 += k0;  x1 += k1  + 3u;
    TFR(17) TFR(29) TFR(16) TFR(24)  x0 += k1;  x1 += ks2 + 4u;
    TFR(13) TFR(15) TFR(26) TFR(6)   x0 += ks2; x1 += k0  + 5u;
#undef TFR
    o0 = x0; o1 = x1;
}

__device__ __forceinline__ uint32_t jax_bits32(uint32_t k0, uint32_t k1, uint32_t n) {
    uint32_t o0, o1;
    tf2x32(k0, k1, 0u, n, o0, o1);
    return o0 ^ o1;
}

__device__ __forceinline__ float jax_gumbel(uint32_t bits) {
    float f = __uint_as_float((bits >> 9) | 0x3f800000u) - 1.0f;
    float u = fmaxf(f, 1.17549435e-38f);
    float nl = -logf(u);               // accurate: u->1 tail decides winners
    return -__logf(nl);
}

// pack (value, idx) so max() == argmax, first-index tie-break
__device__ __forceinline__ u64 pack_vi(float v, int idx) {
    uint32_t s = __float_as_uint(v);
    s = (s & 0x80000000u) ? ~s : (s | 0x80000000u);
    return ((u64)s << 32) | (uint32_t)(0xFFFFFFFFu - (uint32_t)idx);
}

// ---------------- prep kernels ----------------------------------------------
__global__ void transpose_k(const float* __restrict__ emb) {
    __shared__ float t[32][33];
    int rb = blockIdx.x * 32, kb = blockIdx.y * 32;
    int tx = threadIdx.x, ty = threadIdx.y;
#pragma unroll
    for (int j = 0; j < 4; j++)
        t[ty + j * 8][tx] = emb[(rb + ty + j * 8) * NDIM + kb + tx];
    __syncthreads();
#pragma unroll
    for (int j = 0; j < 4; j++)
        g_embT[(kb + ty + j * 8) * NB + rb + tx] = t[tx][ty + j * 8];
}

__global__ void norm_k(const float* __restrict__ emb) {
    int gid = blockIdx.x * blockDim.x + threadIdx.x;
    if (gid < NCLASS) g_ccnt[gid] = 0;          // reset class bins each launch
    int w = gid >> 5;
    int lane = threadIdx.x & 31;
    if (w >= NB) return;
    float4 v = *(const float4*)(emb + w * NDIM + lane * 4);
    float s = v.x * v.x + v.y * v.y + v.z * v.z + v.w * v.w;
#pragma unroll
    for (int o = 16; o; o >>= 1) s += __shfl_xor_sync(0xFFFFFFFFu, s, o);
    if (lane == 0) { g_sqnorm[w] = s; g_best[w] = 0ull; }   // reset every launch
}

__global__ void bin_k(const int* __restrict__ labels) {
    int i = blockIdx.x * blockDim.x + threadIdx.x;
    if (i >= NB) return;
    int c = labels[i];
    int s = atomicAdd(&g_ccnt[c], 1);
    if (s < MAXMEM) g_members[c * MAXMEM + s] = i;
}

// ---------------- negatives: 64x64 triangular tiles, FFMA2 4x4, staged ------
__global__ void __launch_bounds__(NTHREADS, 4)
neg_sample_k(const int* __restrict__ labels, uint32_t kn0, uint32_t kn1) {
    extern __shared__ char sm[];
    float* A_s = (float*)sm;                        // [KS][BT] k-major, tile I
    float* B_s = A_s + KS * BT;                     // [KS][BT] k-major, tile J
    int*   labA = (int*)(B_s + KS * BT);            // [64]
    int*   labB = labA + BT;                        // [64]
    float* sqA  = (float*)(labB + BT);              // [64]
    float* sqB  = sqA + BT;                         // [64]
    u64*   redA = (u64*)(sqB + BT);                 // [64]
    u64*   redB = redA + BT;                        // [64]

    const int tid = threadIdx.x;
    const int tr = tid >> 4;          // 0..15, rows tr*4..+3
    const int tc = tid & 15;          // 0..15, cols tc*4..+3

    // decode triangular pair index
    int bid = blockIdx.x;
    int I = (int)((2.0f * NRT + 1.0f
                   - sqrtf((2.0f * NRT + 1.0f) * (2.0f * NRT + 1.0f)
                           - 8.0f * (float)bid)) * 0.5f);
    while (I * (2 * NRT + 1 - I) / 2 > bid) I--;
    while ((I + 1) * (2 * NRT - I) / 2 <= bid) I++;
    const int J = I + (bid - I * (2 * NRT + 1 - I) / 2);
    const int row0 = I * BT;
    const int col0 = J * BT;
    const bool diag = (I == J);

    if (tid < BT) {
        labA[tid] = labels[row0 + tid]; sqA[tid] = g_sqnorm[row0 + tid];
        redA[tid] = 0ull;
    } else if (tid < 2 * BT) {
        int q = tid - BT;
        labB[q] = labels[col0 + q]; sqB[q] = g_sqnorm[col0 + q];
        redB[q] = 0ull;
    }

    u64 acc2[4][2];
#pragma unroll
    for (int r = 0; r < 4; r++) { acc2[r][0] = 0ull; acc2[r][1] = 0ull; }

    for (int st = 0; st < NDIM / KS; st++) {
        const int k0 = st * KS;
        __syncthreads();
        // load k-stage of both tiles (coalesced float4)
        for (int idx = tid; idx < KS * BT / 4; idx += NTHREADS) {
            int k = idx >> 4;             // BT/4 = 16 float4 per row
            int q = (idx & 15) << 2;
            *(float4*)&A_s[k * BT + q] =
                *(const float4*)&g_embT[(k0 + k) * NB + row0 + q];
            *(float4*)&B_s[k * BT + q] =
                *(const float4*)&g_embT[(k0 + k) * NB + col0 + q];
        }
        __syncthreads();

#pragma unroll 8
        for (int k = 0; k < KS; k++) {
            float4 a = *(const float4*)&A_s[k * BT + (tr << 2)];
            ulonglong2 b2 = *(const ulonglong2*)&B_s[k * BT + (tc << 2)];
            u64 ad0 = dup_f32(a.x), ad1 = dup_f32(a.y);
            u64 ad2 = dup_f32(a.z), ad3 = dup_f32(a.w);
            acc2[0][0] = ffma2(ad0, b2.x, acc2[0][0]);
            acc2[0][1] = ffma2(ad0, b2.y, acc2[0][1]);
            acc2[1][0] = ffma2(ad1, b2.x, acc2[1][0]);
            acc2[1][1] = ffma2(ad1, b2.y, acc2[1][1]);
            acc2[2][0] = ffma2(ad2, b2.x, acc2[2][0]);
            acc2[2][1] = ffma2(ad2, b2.y, acc2[2][1]);
            acc2[3][0] = ffma2(ad3, b2.x, acc2[3][0]);
            acc2[3][1] = ffma2(ad3, b2.y, acc2[3][1]);
        }
    }
    __syncthreads();

    float sqr[4]; int labr[4];
#pragma unroll
    for (int r = 0; r < 4; r++) {
        sqr[r]  = sqA[tr * 4 + r];
        labr[r] = labA[tr * 4 + r];
    }

    u64 best1[4] = {0ull, 0ull, 0ull, 0ull};   // per row (anchor i)
    u64 best2[4] = {0ull, 0ull, 0ull, 0ull};   // per col (anchor j)

#pragma unroll
    for (int cp = 0; cp < 2; cp++) {
#pragma unroll
        for (int h = 0; h < 2; h++) {
            const int cl = tc * 4 + 2 * cp + h;
            const int j  = col0 + cl;
            const int labj = labB[cl];
            const float sqj = sqB[cl];
#pragma unroll
            for (int r = 0; r < 4; r++) {
                if (labr[r] == labj) continue;      // same-label -> -inf logit
                union { u64 u; float2 f; } cv; cv.u = acc2[r][cp];
                const float dot = h ? cv.f.y : cv.f.x;
                const int i = row0 + tr * 4 + r;
                float d2 = (sqr[r] + sqj) - 2.0f * dot;
                d2 = fmaxf(d2, 0.25f);              // == clip d at 0.5
                d2 = fminf(d2, 3.999f);             // guard log(<=0); never hit
                float lq = -63.0f * __logf(d2)
                           - 62.5f * __logf(fmaf(-0.25f, d2, 1.0f));
                {   // orientation 1: anchor i, candidate j
                    uint32_t bits = jax_bits32(kn0, kn1, (uint32_t)(i * NB + j));
                    u64 p = pack_vi(lq + jax_gumbel(bits), j);
                    if (p > best1[r]) best1[r] = p;
                }
                if (!diag) {  // orientation 2: anchor j, candidate i
                    uint32_t bits = jax_bits32(kn0, kn1, (uint32_t)(j * NB + i));
                    u64 p = pack_vi(lq + jax_gumbel(bits), i);
                    if (p > best2[2 * cp + h]) best2[2 * cp + h] = p;
                }
            }
        }
    }

#pragma unroll
    for (int r = 0; r < 4; r++)
        if (best1[r]) atomicMax(&redA[tr * 4 + r], best1[r]);
    if (!diag) {
#pragma unroll
        for (int c = 0; c < 4; c++)
            if (best2[c]) atomicMax(&redB[tc * 4 + c], best2[c]);
    }
    __syncthreads();
    if (tid < BT) {
        if (redA[tid]) atomicMax(&g_best[row0 + tid], redA[tid]);
    } else if (tid < 2 * BT && !diag) {
        int q = tid - BT;
        if (redB[q]) atomicMax(&g_best[col0 + q], redB[q]);
    }
}

// ---------------- positives: warp-per-anchor over class member list ---------
__global__ void pos_sample_k(const int* __restrict__ labels,
                             uint32_t kp0, uint32_t kp1) {
    const int t = threadIdx.x;
    const int anchor = (blockIdx.x * 256 + t) >> 5;
    const int lane = t & 31;
    const int li = labels[anchor];
    const int cnt = min(g_ccnt[li], MAXMEM);
    u64 best = 0ull;
    for (int s = lane; s < cnt; s += 32) {
        int j = g_members[li * MAXMEM + s];
        if (j != anchor) {
            uint32_t bits = jax_bits32(kp0, kp1, (uint32_t)(anchor * NB + j));
            u64 p = pack_vi(jax_gumbel(bits), j);
            if (p > best) best = p;
        }
    }
#pragma unroll
    for (int o = 16; o; o >>= 1) {
        u64 q = __shfl_xor_sync(0xFFFFFFFFu, best, o);
        if (q > best) best = q;
    }
    if (lane == 0)
        g_posidx[anchor] = (int)(0xFFFFFFFFu - (uint32_t)best);
}

// ---------------- finalize: per-anchor losses -------------------------------
__global__ void finalize_k(const float* __restrict__ emb,
                           const int* __restrict__ labels,
                           const float* __restrict__ beta) {
    int w = (blockIdx.x * blockDim.x + threadIdx.x) >> 5;
    int lane = threadIdx.x & 31;
    if (w >= NB) return;
    int pi = g_posidx[w];
    int ni = (int)(0xFFFFFFFFu - (uint32_t)g_best[w]);
    float4 a = *(const float4*)(emb + w * NDIM + lane * 4);
    float4 p = *(const float4*)(emb + pi * NDIM + lane * 4);
    float4 n = *(const float4*)(emb + ni * NDIM + lane * 4);
    float dx, sap, san;
    dx = a.x - p.x; sap = dx * dx; dx = a.y - p.y; sap += dx * dx;
    dx = a.z - p.z; sap += dx * dx; dx = a.w - p.w; sap += dx * dx;
    dx = a.x - n.x; san = dx * dx; dx = a.y - n.y; san += dx * dx;
    dx = a.z - n.z; san += dx * dx; dx = a.w - n.w; san += dx * dx;
#pragma unroll
    for (int o = 16; o; o >>= 1) {
        sap += __shfl_xor_sync(0xFFFFFFFFu, sap, o);
        san += __shfl_xor_sync(0xFFFFFFFFu, san, o);
    }
    if (lane == 0) {
        float d_ap = sqrtf(sap + 1e-8f);
        float d_an = sqrtf(san + 1e-8f);
        float ba = beta[labels[w]];
        float pl = fmaxf(d_ap - ba + 0.2f, 0.0f);
        float nl = fmaxf(ba - d_an + 0.2f, 0.0f);
        g_loss[w] = pl + nl;
        g_cnt[w]  = (pl > 0.0f ? 1.0f : 0.0f) + (nl > 0.0f ? 1.0f : 0.0f);
    }
}

__global__ void reduce_k(float* __restrict__ out) {
    __shared__ float st[256], sc[256];
    int t = threadIdx.x;
    float s = 0.f, c = 0.f;
    for (int i = t; i < NB; i += 256) { s += g_loss[i]; c += g_cnt[i]; }
    st[t] = s; sc[t] = c;
    __syncthreads();
    for (int o = 128; o; o >>= 1) {
        if (t < o) { st[t] += st[t + o]; sc[t] += sc[t + o]; }
        __syncthreads();
    }
    if (t == 0) out[0] = (sc[0] == 0.0f) ? st[0] : st[0] / sc[0];
}

// ---------------- host -------------------------------------------------------
extern "C" void kernel_launch(void* const* d_in, const int* in_sizes, int n_in,
                              void* d_out, int out_size) {
    const float* emb    = (const float*)d_in[0];
    const int*   labels = (const int*)d_in[1];
    const float* beta   = (const float*)d_in[2];
    float* out = (float*)d_out;

    uint32_t kn0, kn1, kp0, kp1;
    tf2x32(0u, 42u, 0u, 0u, kn0, kn1);   // foldlike split: k_neg
    tf2x32(0u, 42u, 0u, 1u, kp0, kp1);   // k_pos

    const int smem = 2 * (KS * BT * 4)          // A_s, B_s
                   + 2 * (BT * 4)               // labA, labB
                   + 2 * (BT * 4)               // sqA, sqB
                   + 2 * (BT * 8);              // redA, redB
    cudaFuncSetAttribute(neg_sample_k,
                         cudaFuncAttributeMaxDynamicSharedMemorySize, smem);

    transpose_k<<<dim3(NB / 32, NDIM / 32), dim3(32, 8)>>>(emb);
    norm_k<<<NB * 32 / 256, 256>>>(emb);
    bin_k<<<NB / 256, 256>>>(labels);
    neg_sample_k<<<NPAIRS, NTHREADS, smem>>>(labels, kn0, kn1);
    pos_sample_k<<<NB / 8, 256>>>(labels, kp0, kp1);
    finalize_k<<<NB * 32 / 256, 256>>>(emb, labels, beta);
    reduce_k<<<1, 256>>>(out);
}